// round 7
// baseline (speedup 1.0000x reference)
#include <cuda_runtime.h>
#include <cuda_bf16.h>

// Problem constants (shapes are fixed by the dataset)
#define NFEAT 256
#define NHID  256
#define NOUT  128
#define MAX_NODES 50000

// Scratch (no cudaMalloc allowed) — ~128 MB total
__device__ float g_sup1[(size_t)MAX_NODES * NHID];   // X @ W1
__device__ float g_agg1[(size_t)MAX_NODES * NHID];   // segment_sum(sup1[src])
__device__ float g_sup2[(size_t)MAX_NODES * NOUT];   // relu(agg1) @ W2

// ---------------------------------------------------------------------------
// Tiled fp32 GEMM: C[M,N] = op(A)[M,K] @ B[K,N]
// BM=BN=64, BK=16, 256 threads, 4x4 micro-tile per thread.
// RELU_A applies relu to A elements on load (fuses the inter-layer ReLU).
// ---------------------------------------------------------------------------
template<bool RELU_A>
__global__ __launch_bounds__(256)
void sgemm_kernel(const float* __restrict__ A, const float* __restrict__ B,
                  float* __restrict__ C, int M, int N, int K)
{
    __shared__ float As[16][64];   // transposed A tile: As[k][m]
    __shared__ float Bs[16][64];   // Bs[k][n]

    const int tid = threadIdx.x;
    const int m0  = blockIdx.x * 64;
    const int n0  = blockIdx.y * 64;

    // compute micro-tile coords
    const int tr = tid / 16;          // 0..15 -> rows tr*4..tr*4+3
    const int tc = tid % 16;          // 0..15 -> cols tc*4..tc*4+3

    // A tile load coords: 64 rows x 16 cols, one float4 per thread
    const int ar = tid / 4;           // 0..63
    const int ac = (tid % 4) * 4;     // 0,4,8,12
    // B tile load coords: 16 rows x 64 cols, one float4 per thread
    const int br = tid / 16;          // 0..15
    const int bc = (tid % 16) * 4;    // 0..60

    float acc[4][4];
#pragma unroll
    for (int i = 0; i < 4; i++)
#pragma unroll
        for (int j = 0; j < 4; j++) acc[i][j] = 0.0f;

    for (int k0 = 0; k0 < K; k0 += 16) {
        // --- load A tile (guard M), store transposed ---
        float4 a4 = make_float4(0.f, 0.f, 0.f, 0.f);
        const int gm = m0 + ar;
        if (gm < M)
            a4 = *reinterpret_cast<const float4*>(A + (long long)gm * K + k0 + ac);
        if (RELU_A) {
            a4.x = fmaxf(a4.x, 0.f); a4.y = fmaxf(a4.y, 0.f);
            a4.z = fmaxf(a4.z, 0.f); a4.w = fmaxf(a4.w, 0.f);
        }
        As[ac + 0][ar] = a4.x;
        As[ac + 1][ar] = a4.y;
        As[ac + 2][ar] = a4.z;
        As[ac + 3][ar] = a4.w;

        // --- load B tile ---
        float4 b4 = *reinterpret_cast<const float4*>(B + (long long)(k0 + br) * N + n0 + bc);
        *reinterpret_cast<float4*>(&Bs[br][bc]) = b4;

        __syncthreads();

#pragma unroll
        for (int k = 0; k < 16; k++) {
            float a[4], b[4];
            *reinterpret_cast<float4*>(a) = *reinterpret_cast<const float4*>(&As[k][tr * 4]);
            *reinterpret_cast<float4*>(b) = *reinterpret_cast<const float4*>(&Bs[k][tc * 4]);
#pragma unroll
            for (int i = 0; i < 4; i++)
#pragma unroll
                for (int j = 0; j < 4; j++)
                    acc[i][j] = fmaf(a[i], b[j], acc[i][j]);
        }
        __syncthreads();
    }

    // --- store C ---
#pragma unroll
    for (int i = 0; i < 4; i++) {
        const int row = m0 + tr * 4 + i;
        if (row < M) {
            float4 o = make_float4(acc[i][0], acc[i][1], acc[i][2], acc[i][3]);
            *reinterpret_cast<float4*>(C + (long long)row * N + n0 + tc * 4) = o;
        }
    }
}

// ---------------------------------------------------------------------------
// Edge scatter-add: for each edge e, out[dst[e]] += sup[src[e]]  (row of V
// float4s, i.e. 4*V floats). Uses red.global.add.v4.f32 (sm_90+, no return).
// V = float4s per row (64 for 256 cols, 32 for 128 cols).
// ---------------------------------------------------------------------------
template<int V, int LOGV>
__global__ __launch_bounds__(256)
void scatter_kernel(const float* __restrict__ sup,
                    const int* __restrict__ src,
                    const int* __restrict__ dst,
                    float* __restrict__ out, int n_edges)
{
    const int total  = n_edges << LOGV;                 // < 2^31 (800k * 64)
    const int stride = gridDim.x * blockDim.x;
    const float4* sup4 = reinterpret_cast<const float4*>(sup);

    for (int i = blockIdx.x * blockDim.x + threadIdx.x; i < total; i += stride) {
        const int e = i >> LOGV;
        const int j = i & (V - 1);
        const int s = __ldg(src + e);
        const int d = __ldg(dst + e);
        const float4 v = __ldg(sup4 + (long long)s * V + j);
        float* p = out + (((long long)d * V + j) << 2);
        asm volatile("red.global.add.v4.f32 [%0], {%1, %2, %3, %4};"
                     :: "l"(p), "f"(v.x), "f"(v.y), "f"(v.z), "f"(v.w)
                     : "memory");
    }
}

extern "C" void kernel_launch(void* const* d_in, const int* in_sizes, int n_in,
                              void* d_out, int out_size)
{
    const float* x    = (const float*)d_in[0];   // [N, 256]
    const float* w1   = (const float*)d_in[1];   // [256, 256]
    const float* w2   = (const float*)d_in[2];   // [256, 128]
    const int*   esrc = (const int*)d_in[3];     // [E]
    const int*   edst = (const int*)d_in[4];     // [E]

    const int M = in_sizes[0] / NFEAT;   // 50000 nodes
    const int E = in_sizes[3];           // 800000 edges

    float *sup1, *agg1, *sup2;
    cudaGetSymbolAddress((void**)&sup1, g_sup1);
    cudaGetSymbolAddress((void**)&agg1, g_agg1);
    cudaGetSymbolAddress((void**)&sup2, g_sup2);

    // zero accumulation targets (graph-capturable memsets)
    cudaMemsetAsync(agg1, 0, (size_t)M * NHID * sizeof(float));
    cudaMemsetAsync(d_out, 0, (size_t)out_size * sizeof(float));

    const dim3 tb(256);
    const int mblk = (M + 63) / 64;

    // layer 1: sup1 = X @ W1
    sgemm_kernel<false><<<dim3(mblk, NHID / 64), tb>>>(x, w1, sup1, M, NHID, NFEAT);
    // agg1[dst] += sup1[src]   (256 floats = 64 float4 per edge)
    scatter_kernel<64, 6><<<4736, 256>>>(sup1, esrc, edst, agg1, E);
    // layer 2: sup2 = relu(agg1) @ W2
    sgemm_kernel<true><<<dim3(mblk, NOUT / 64), tb>>>(agg1, w2, sup2, M, NOUT, NHID);
    // out[dst] += sup2[src]    (128 floats = 32 float4 per edge)
    scatter_kernel<32, 5><<<4736, 256>>>(sup2, esrc, edst, (float*)d_out, E);
}